// round 16
// baseline (speedup 1.0000x reference)
#include <cuda_runtime.h>
#include <cuda_bf16.h>
#include <cstdint>

#define N_NODES 50000
#define N_EDGES 800000
#define NUM_RELS 16
#define IN_DIM 128
#define H_DIM 128
#define OUT_DIM 64

#define TM 64                        // node tile
#define N_TILES 782                  // ceil(50000/64)
#define NPAD (N_TILES * 64)          // 50048
#define NBINS (N_TILES * NUM_RELS)   // 12512
#define BIN_CAP 160                  // fixed bin capacity (Poisson(64) tail ~1e-25)
#define XBLKS ((NPAD * 64) / 256)    // 12512 prep blocks
#define HZ4 ((N_NODES * H_DIM) / 4)  // float4 count of H
#define HBLKS ((HZ4 + 255) / 256)    // 6250

// ---------------------------------------------------------------------------
// Scratch (device globals: allocation-free rule)
// ---------------------------------------------------------------------------
__device__ float g_H[(size_t)N_NODES * H_DIM];      // 25.6 MB
__device__ int    g_binCur[NBINS];
__device__ float4 g_pack[(size_t)NBINS * BIN_CAP];  // 32 MB, slot = bin*CAP+pos
// Pre-split images, plain layout: row = 256 bf16 = [0:128) hi | [128:256) lo
__device__ __nv_bfloat16 g_X [(size_t)NPAD * 256];  // X or H split, 25.6 MB
__device__ __nv_bfloat16 g_W1[NUM_RELS * 128 * 256];// W1^T split (n-major), 1 MB
__device__ __nv_bfloat16 g_W2[NUM_RELS * 64 * 256]; // W2^T split, 0.5 MB

// ---------------------------------------------------------------------------
// Warp-MMA helpers (baseline PTX: legal on plain sm_103 target)
// ---------------------------------------------------------------------------
__device__ __forceinline__ void ldsm_x4(uint32_t r[4], uint32_t addr) {
    asm volatile("ldmatrix.sync.aligned.m8n8.x4.shared.b16 {%0,%1,%2,%3}, [%4];"
                 : "=r"(r[0]), "=r"(r[1]), "=r"(r[2]), "=r"(r[3]) : "r"(addr));
}
__device__ __forceinline__ void mma_bf16(float c[4], const uint32_t a[4],
                                         uint32_t b0, uint32_t b1) {
    asm volatile("mma.sync.aligned.m16n8k16.row.col.f32.bf16.bf16.f32 "
                 "{%0,%1,%2,%3}, {%4,%5,%6,%7}, {%8,%9}, {%0,%1,%2,%3};"
                 : "+f"(c[0]), "+f"(c[1]), "+f"(c[2]), "+f"(c[3])
                 : "r"(a[0]), "r"(a[1]), "r"(a[2]), "r"(a[3]), "r"(b0), "r"(b1));
}

// ---------------------------------------------------------------------------
// combo prep: W1+W2 -> split W^T images (n-major rows of 256: hi|lo);
// also zeroes bin cursors. grid (NUM_RELS, 2): y==0 -> W1 (+reset), y==1 -> W2.
// ---------------------------------------------------------------------------
__global__ __launch_bounds__(256)
void combo_prep_kernel(const float* __restrict__ W1, const float* __restrict__ W2,
                       __nv_bfloat16* __restrict__ w1img,
                       __nv_bfloat16* __restrict__ w2img,
                       int* __restrict__ cur)
{
    const int r = blockIdx.x, tid = threadIdx.x;
    const int OUTD = blockIdx.y == 0 ? 128 : 64;
    const float* Wr = (blockIdx.y == 0 ? W1 : W2) + (size_t)r * 128 * OUTD;
    __nv_bfloat16* img = (blockIdx.y == 0 ? w1img : w2img) + (size_t)r * OUTD * 256;
    for (int i = tid; i < OUTD * 128; i += 256) {
        int n = i >> 7, k = i & 127;
        float x = Wr[(size_t)k * OUTD + n];
        __nv_bfloat16 h = __float2bfloat16(x);
        __nv_bfloat16 l = __float2bfloat16(x - __bfloat162float(h));
        img[n * 256 + k] = h;
        img[n * 256 + 128 + k] = l;
    }
    if (blockIdx.y == 0) {
        for (int i = r * 256 + tid; i < NBINS; i += NUM_RELS * 256)
            cur[i] = 0;
    }
}

// ---------------------------------------------------------------------------
// Single-pass edge binning: key = (src>>6)*16 + etype, slot = bin*CAP + pos.
// ---------------------------------------------------------------------------
__global__ void bin_fill_kernel(const int* __restrict__ src,
                                const int* __restrict__ dstv,
                                const int* __restrict__ et,
                                const float* __restrict__ norm,
                                int* __restrict__ cur,
                                float4* __restrict__ pack)
{
    int e = blockIdx.x * 256 + threadIdx.x;
    if (e >= N_EDGES) return;
    int s = src[e];
    int bin = (s >> 6) * NUM_RELS + et[e];
    int pos = atomicAdd(&cur[bin], 1);
    if (pos < BIN_CAP) {
        float4 p;
        p.x = __int_as_float(s & 63);
        p.y = __int_as_float(dstv[e]);
        p.z = norm[e];
        p.w = 0.f;
        pack[(size_t)bin * BIN_CAP + pos] = p;
    }
}

// ---------------------------------------------------------------------------
// prep_x: fp32 [N,128] -> split hi/lo image (optional fused ReLU); extra
// grid blocks zero an accumulator buffer.
// ---------------------------------------------------------------------------
template<int RELU>
__global__ __launch_bounds__(256)
void prep_x_kernel(const float* __restrict__ X, __nv_bfloat16* __restrict__ img,
                   float4* __restrict__ zbuf, int zn4)
{
    const int b = blockIdx.x;
    if (b < XBLKS) {
        int i = b * 256 + threadIdx.x;       // < NPAD * 64
        int n = i >> 6, k = (i & 63) * 2;
        float2 v = make_float2(0.f, 0.f);
        if (n < N_NODES) v = *(const float2*)(X + (size_t)n * 128 + k);
        if (RELU) { v.x = fmaxf(v.x, 0.f); v.y = fmaxf(v.y, 0.f); }
        __nv_bfloat16 h0 = __float2bfloat16(v.x), h1 = __float2bfloat16(v.y);
        __nv_bfloat16 l0 = __float2bfloat16(v.x - __bfloat162float(h0));
        __nv_bfloat16 l1 = __float2bfloat16(v.y - __bfloat162float(h1));
        size_t o = (size_t)n * 256 + k;
        __nv_bfloat162 hh; hh.x = h0; hh.y = h1;
        __nv_bfloat162 ll; ll.x = l0; ll.y = l1;
        *(__nv_bfloat162*)&img[o] = hh;
        *(__nv_bfloat162*)&img[o + 128] = ll;
    } else {
        int i = (b - XBLKS) * 256 + threadIdx.x;
        if (i < zn4) zbuf[i] = make_float4(0.f, 0.f, 0.f, 0.f);
    }
}

// ---------------------------------------------------------------------------
// Fused transform+scatter, rel-outer / tile-inner, N split over blockIdx.z:
//   each block owns a 64-column slice [zoff, zoff+64) of W[rel]. B panels
//   are 64 rows -> smem 69.6 KB -> 3 blocks/SM for BOTH layers, so the
//   stage/MMA/epilogue/scatter phases of different blocks overlap.
// ---------------------------------------------------------------------------
template<int OUTD>
__global__ __launch_bounds__(256, 3)
void fused_transform_kernel(const __nv_bfloat16* __restrict__ Ximg,
                            const __nv_bfloat16* __restrict__ Wimg,
                            float* __restrict__ accOut,
                            const float4* __restrict__ pack,
                            const int* __restrict__ binCur)
{
    constexpr int LDA = 136;                 // padded bf16 stride
    constexpr int LDB = 136;
    constexpr int A_PANEL = TM * LDA;        // elems
    constexpr int B_PANEL = 64 * LDB;        // 64-col slice
    constexpr int LDT = 68;                  // fp32 tile stride (64 + 4)

    extern __shared__ __nv_bfloat16 sm[];
    __nv_bfloat16* sAhi = sm;
    __nv_bfloat16* sAlo = sm + A_PANEL;
    __nv_bfloat16* sBhi = sm + 2 * A_PANEL;
    __nv_bfloat16* sBlo = sBhi + B_PANEL;
    float* sTile = (float*)sm;               // overlays A panels after MMA

    constexpr int WM = 32;                   // TM / 2 (2 warp rows)
    constexpr int WN = 16;                   // 64 / 4 (4 warp cols)
    constexpr int MFR = 2;
    constexpr int NFR = 2;

    const int tid = threadIdx.x, wid = tid >> 5, lane = tid & 31;
    const int wm0 = (wid >> 2) * WM;
    const int wn0 = (wid & 3) * WN;
    const int rel = blockIdx.y;
    const int zoff = blockIdx.z * 64;        // column slice base (0 for OUTD=64)
    const int lr = lane & 15, lh = lane >> 4;

    const uint32_t aHiBase = (uint32_t)__cvta_generic_to_shared(sAhi);
    const uint32_t aLoBase = (uint32_t)__cvta_generic_to_shared(sAlo);
    const uint32_t bHiBase = (uint32_t)__cvta_generic_to_shared(sBhi);
    const uint32_t bLoBase = (uint32_t)__cvta_generic_to_shared(sBlo);

    const uint32_t aRow0 = (uint32_t)(((wm0 + lr) * LDA) << 1);
    const uint32_t aRow1 = (uint32_t)(((wm0 + 16 + lr) * LDA) << 1);
    const uint32_t bRow0 = (uint32_t)(((wn0 + lr) * LDB) << 1);

    // ---- Stage B slice ONCE: rows [zoff, zoff+64) of W image (hi|lo rows)
    {
        const __nv_bfloat16* gW = Wimg + ((size_t)rel * OUTD + zoff) * 256;
        for (int i = tid; i < 64 * 32; i += 256) {
            int row = i >> 5, c = i & 31;
            float4 v = *(const float4*)(gW + row * 256 + c * 8);
            if (c < 16) *(float4*)&sBhi[row * LDB + c * 8] = v;
            else        *(float4*)&sBlo[row * LDB + (c - 16) * 8] = v;
        }
    }

    for (int t = blockIdx.x; t < N_TILES; t += gridDim.x) {
        __syncthreads();   // prior scatter done -> A/tile region free
        // ---- Stage A panels for tile t (float4 copy from split image)
        {
            const __nv_bfloat16* gA = Ximg + (size_t)t * TM * 256;
            for (int i = tid; i < TM * 32; i += 256) {
                int row = i >> 5, c = i & 31;
                float4 v = *(const float4*)(gA + row * 256 + c * 8);
                if (c < 16) *(float4*)&sAhi[row * LDA + c * 8] = v;
                else        *(float4*)&sAlo[row * LDA + (c - 16) * 8] = v;
            }
        }
        __syncthreads();   // A (and B on first iter) visible

        // ---- MMA: tile = A @ W^T slice, split bf16, 3 products into one acc
        float acc[MFR][NFR][4];
        #pragma unroll
        for (int mi = 0; mi < MFR; mi++)
            #pragma unroll
            for (int ni = 0; ni < NFR; ni++)
                #pragma unroll
                for (int q = 0; q < 4; q++) acc[mi][ni][q] = 0.f;

        #pragma unroll
        for (int k = 0; k < 8; k++) {
            const uint32_t kofs = (uint32_t)((k * 16 + lh * 8) << 1);
            uint32_t ah[MFR][4], al[MFR][4], bh[4], bl[4];
            ldsm_x4(ah[0], aHiBase + aRow0 + kofs);
            ldsm_x4(al[0], aLoBase + aRow0 + kofs);
            ldsm_x4(ah[1], aHiBase + aRow1 + kofs);
            ldsm_x4(al[1], aLoBase + aRow1 + kofs);
            ldsm_x4(bh, bHiBase + bRow0 + kofs);
            ldsm_x4(bl, bLoBase + bRow0 + kofs);
            #pragma unroll
            for (int mi = 0; mi < MFR; mi++)
                #pragma unroll
                for (int ni = 0; ni < NFR; ni++) {
                    mma_bf16(acc[mi][ni], ah[mi], bh[ni], bh[2 + ni]);
                    mma_bf16(acc[mi][ni], ah[mi], bl[ni], bl[2 + ni]);
                    mma_bf16(acc[mi][ni], al[mi], bh[ni], bh[2 + ni]);
                }
        }
        __syncthreads();   // all warps done reading A -> overlay tile

        // ---- Epilogue: acc -> fp32 smem tile (64 rows x 64 cols, LDT=68)
        #pragma unroll
        for (int mi = 0; mi < MFR; mi++)
            #pragma unroll
            for (int ni = 0; ni < NFR; ni++) {
                int row = wm0 + mi * 16 + (lane >> 2);
                int col = wn0 + ni * 8 + (lane & 3) * 2;
                *(float2*)&sTile[row * LDT + col] =
                    make_float2(acc[mi][ni][0], acc[mi][ni][1]);
                *(float2*)&sTile[(row + 8) * LDT + col] =
                    make_float2(acc[mi][ni][2], acc[mi][ni][3]);
            }
        __syncthreads();   // tile visible

        // ---- Scatter bin (t, rel): accOut[dst, zoff:zoff+64] += tile[row]*norm
        {
            const int bin = t * NUM_RELS + rel;
            const size_t off = (size_t)bin * BIN_CAP;
            int cnt = binCur[bin];
            if (cnt > BIN_CAP) cnt = BIN_CAP;
            const int sub = lane >> 4, l = lane & 15;   // 2 edges per warp
            for (int j = wid * 2; j < cnt; j += 16) {
                int jj = j + sub;
                if (jj < cnt) {
                    float4 pk = pack[off + jj];
                    int row = __float_as_int(pk.x);
                    int d   = __float_as_int(pk.y);
                    float nv = pk.z;
                    float4 v = *(const float4*)&sTile[row * LDT + l * 4];
                    v.x *= nv; v.y *= nv; v.z *= nv; v.w *= nv;
                    float* p = accOut + (size_t)d * OUTD + zoff + l * 4;
                    asm volatile("red.global.add.v4.f32 [%0], {%1, %2, %3, %4};"
                                 :: "l"(p), "f"(v.x), "f"(v.y), "f"(v.z), "f"(v.w)
                                 : "memory");
                }
            }
        }
    }
}

extern "C" void kernel_launch(void* const* d_in, const int* in_sizes, int n_in,
                              void* d_out, int out_size)
{
    const float* feat = (const float*)d_in[0];
    const float* norm = (const float*)d_in[1];
    const float* W1   = (const float*)d_in[2];
    const float* W2   = (const float*)d_in[3];
    const int*   src  = (const int*)d_in[4];
    const int*   dst  = (const int*)d_in[5];
    const int*   et   = (const int*)d_in[6];
    float*       out  = (float*)d_out;

    float *H;
    int *binCur;
    float4 *pack;
    __nv_bfloat16 *Ximg, *W1img, *W2img;
    cudaGetSymbolAddress((void**)&H,      g_H);
    cudaGetSymbolAddress((void**)&binCur, g_binCur);
    cudaGetSymbolAddress((void**)&pack,   g_pack);
    cudaGetSymbolAddress((void**)&Ximg,   g_X);
    cudaGetSymbolAddress((void**)&W1img,  g_W1);
    cudaGetSymbolAddress((void**)&W2img,  g_W2);

    // smem: A panels (hi+lo, also fp32 tile overlay) + B slice (hi+lo)
    constexpr int SMEM = (2 * TM * 136 + 2 * 64 * 136) * 2;  // 69632
    cudaFuncSetAttribute(fused_transform_kernel<H_DIM>,
                         cudaFuncAttributeMaxDynamicSharedMemorySize, SMEM);
    cudaFuncSetAttribute(fused_transform_kernel<OUT_DIM>,
                         cudaFuncAttributeMaxDynamicSharedMemorySize, SMEM);

    // 1: weight prep + bin cursor reset
    combo_prep_kernel<<<dim3(NUM_RELS, 2), 256>>>(W1, W2, W1img, W2img, binCur);
    // 2: single-pass edge binning (shared by both layers)
    bin_fill_kernel<<<(N_EDGES + 255) / 256, 256>>>(src, dst, et, norm,
                                                    binCur, pack);
    // 3: split feat -> image, zero H
    prep_x_kernel<0><<<XBLKS + HBLKS, 256>>>(feat, Ximg, (float4*)H, HZ4);
    // 4: layer 1 fused (ncu capture lands here): N split in z, 448 blocks
    fused_transform_kernel<H_DIM><<<dim3(14, NUM_RELS, 2), 256, SMEM>>>(
        Ximg, W1img, H, pack, binCur);
    // 5: split relu(H) -> image
    prep_x_kernel<1><<<XBLKS, 256>>>(H, Ximg, nullptr, 0);
    // 6: zero output (harness poisons to 0xAA)
    cudaMemsetAsync(out, 0, (size_t)out_size * sizeof(float));
    // 7: layer 2 fused: 448 blocks
    fused_transform_kernel<OUT_DIM><<<dim3(28, NUM_RELS, 1), 256, SMEM>>>(
        Ximg, W2img, out, pack, binCur);
}